// round 7
// baseline (speedup 1.0000x reference)
#include <cuda_runtime.h>
#include <cstdint>
#include <math.h>

// Problem dims (fixed)
#define SEQ   1024
#define DH    64
#define HEADS 64          // bz*16
#define MD    1024        // model_dim
#define ND    2048        // model_dim * n_scale
#define MROWS 4096        // bz*seq

// Scratch (allocation-free rule: device globals)
__device__ float g_rp[(size_t)MROWS * ND];            // 32 MB
__device__ float g_ctot[(size_t)HEADS * SEQ * 128];   // 32 MB: ctx1/ctx2 interleaved
__device__ float g_scores[(size_t)HEADS * SEQ * SEQ]; // 256 MB: raw scaled scores

// ---------------------------------------------------------------------------
// Common MMA helpers
// ---------------------------------------------------------------------------
__device__ __forceinline__ uint32_t f2tf32(float x) {
    uint32_t r;
    asm("cvt.rna.tf32.f32 %0, %1;" : "=r"(r) : "f"(x));
    return r;
}

// split x into tf32 hi + tf32 lo (x ~= hi + lo, |lo| <= 2^-11 |x|)
__device__ __forceinline__ void hilo(float x, uint32_t& h, uint32_t& l) {
    h = f2tf32(x);
    l = f2tf32(x - __uint_as_float(h));
}

__device__ __forceinline__ void mma_tf32(float* c, const uint32_t* a, const uint32_t* b) {
    asm volatile(
        "mma.sync.aligned.m16n8k8.row.col.f32.tf32.tf32.f32 "
        "{%0,%1,%2,%3},{%4,%5,%6,%7},{%8,%9},{%0,%1,%2,%3};"
        : "+f"(c[0]), "+f"(c[1]), "+f"(c[2]), "+f"(c[3])
        : "r"(a[0]), "r"(a[1]), "r"(a[2]), "r"(a[3]), "r"(b[0]), "r"(b[1]));
}

__device__ __forceinline__ void cp16(void* smem, const void* gmem) {
    uint32_t s = (uint32_t)__cvta_generic_to_shared(smem);
    asm volatile("cp.async.ca.shared.global [%0], [%1], 16;" :: "r"(s), "l"(gmem));
}
#define CP_COMMIT() asm volatile("cp.async.commit_group;")
#define CP_WAIT1()  asm volatile("cp.async.wait_group 1;")
#define CP_WAIT0()  asm volatile("cp.async.wait_group 0;")

// ---------------------------------------------------------------------------
// TF32 GEMM, cp.async 2-stage double buffer: C = A B^T + bias (+ addend)
// BM=BN=128, BK=16, 256 threads, warp tile 32x64.
// ---------------------------------------------------------------------------
#define GSTR 20

__global__ void __launch_bounds__(256) gemm_tf32(
    const float* __restrict__ A, const float* __restrict__ B,
    const float* __restrict__ bias, const float* __restrict__ addend,
    float* __restrict__ C, int M, int N, int K)
{
    __shared__ float As[2][128 * GSTR];
    __shared__ float Bs[2][128 * GSTR];

    const int tid  = threadIdx.x;
    const int warp = tid >> 5, lane = tid & 31;
    const int wm = (warp >> 1) * 32;
    const int wn = (warp & 1) * 64;
    const int m0 = blockIdx.y * 128, n0 = blockIdx.x * 128;
    const int g  = lane >> 2;
    const int tg = lane & 3;

    float acc[2][8][4];
#pragma unroll
    for (int i = 0; i < 2; i++)
#pragma unroll
        for (int j = 0; j < 8; j++)
#pragma unroll
            for (int r = 0; r < 4; r++) acc[i][j][r] = 0.f;

    // cp.async loader: 512 float4 per tile per matrix, 2 per thread each
    const int r0 = tid >> 1;                 // via idx decomposition below
    (void)r0;

    auto load_stage = [&](int s, int k0) {
#pragma unroll
        for (int i = 0; i < 2; i++) {
            const int idx = tid + 256 * i;
            const int row = idx >> 2;
            const int cq  = (idx & 3) * 4;
            cp16(&As[s][row * GSTR + cq], A + (size_t)(m0 + row) * K + k0 + cq);
            cp16(&Bs[s][row * GSTR + cq], B + (size_t)(n0 + row) * K + k0 + cq);
        }
    };

    const int ntiles = K / 16;
    load_stage(0, 0);
    CP_COMMIT();

    for (int t = 0; t < ntiles; t++) {
        if (t + 1 < ntiles) {
            load_stage((t + 1) & 1, (t + 1) * 16);
            CP_COMMIT();
            CP_WAIT1();
        } else {
            CP_WAIT0();
        }
        __syncthreads();

        const float* Ab = As[t & 1];
        const float* Bb = Bs[t & 1];
#pragma unroll
        for (int ks = 0; ks < 16; ks += 8) {
            uint32_t afrag[2][4], bfrag[8][2];
#pragma unroll
            for (int mi = 0; mi < 2; mi++) {
                const int row = wm + mi * 16 + g;
                afrag[mi][0] = f2tf32(Ab[row * GSTR + ks + tg]);
                afrag[mi][1] = f2tf32(Ab[(row + 8) * GSTR + ks + tg]);
                afrag[mi][2] = f2tf32(Ab[row * GSTR + ks + tg + 4]);
                afrag[mi][3] = f2tf32(Ab[(row + 8) * GSTR + ks + tg + 4]);
            }
#pragma unroll
            for (int ni = 0; ni < 8; ni++) {
                const int col = wn + ni * 8 + g;
                bfrag[ni][0] = f2tf32(Bb[col * GSTR + ks + tg]);
                bfrag[ni][1] = f2tf32(Bb[col * GSTR + ks + tg + 4]);
            }
#pragma unroll
            for (int mi = 0; mi < 2; mi++)
#pragma unroll
                for (int ni = 0; ni < 8; ni++)
                    mma_tf32(acc[mi][ni], afrag[mi], bfrag[ni]);
        }
        __syncthreads();
    }

#pragma unroll
    for (int mi = 0; mi < 2; mi++) {
#pragma unroll
        for (int ni = 0; ni < 8; ni++) {
            const int m = m0 + wm + mi * 16 + g;
            const int n = n0 + wn + ni * 8 + tg * 2;
            const float bx = bias[n], by = bias[n + 1];
            float2 v0 = make_float2(acc[mi][ni][0] + bx, acc[mi][ni][1] + by);
            float2 v1 = make_float2(acc[mi][ni][2] + bx, acc[mi][ni][3] + by);
            if (addend) {
                float2 d0 = *(const float2*)(addend + (size_t)m * N + n);
                float2 d1 = *(const float2*)(addend + (size_t)(m + 8) * N + n);
                v0.x += d0.x; v0.y += d0.y; v1.x += d1.x; v1.y += d1.y;
            }
            *(float2*)(C + (size_t)m * N + n) = v0;
            *(float2*)(C + (size_t)(m + 8) * N + n) = v1;
        }
    }
}

// ---------------------------------------------------------------------------
// Tensor-core attention (tf32x3 = fp32-equivalent precision).
// Block: 128 q rows x one head; 8 warps, warp w owns q rows [16w,16w+16).
// Phase 1: scores = 8*(Q K^T) via mma tf32x3 -> g_scores + streaming (m,l).
// Phase 2: p = exp(s-m)/l from cached scores (read at A-frag positions),
//          optional attn output, ctx = P V via mma tf32x3.
// ---------------------------------------------------------------------------
#define ASTR 68
#define ATTN_SMEM (2 * 128 * ASTR * 4)   // 69,632 B

__global__ void __launch_bounds__(256, 2)
attn_mma(const float* __restrict__ Qbase, int q_head_stride, int q_row_stride,
         const float* __restrict__ Kin, const float* __restrict__ Vin,
         float* __restrict__ scores,
         float* __restrict__ attn_out,   // nullptr for pass 2
         float* __restrict__ ctx_out, int ctx_off)
{
    extern __shared__ float smf[];
    float* sQ  = smf;                // [128][ASTR]
    float* sKV = smf + 128 * ASTR;   // [128][ASTR]  (K in phase 1, V in phase 2)

    const int H   = blockIdx.y;
    const int q0  = blockIdx.x * 128;
    const int tid = threadIdx.x;
    const int w   = tid >> 5, lane = tid & 31;
    const int g   = lane >> 2, tg = lane & 3;
    const int wq  = w * 16;

    const float* Qh = Qbase + (size_t)H * q_head_stride + (size_t)q0 * q_row_stride;
    const float* Kh = Kin + (size_t)H * (SEQ * DH);
    const float* Vh = Vin + (size_t)H * (SEQ * DH);
    float* Sh = scores + (size_t)H * SEQ * SEQ + (size_t)q0 * SEQ;

    // ---- load Q tile (128x64) into smem, coalesced ----
    {
        const int r  = tid >> 1;
        const int c0 = (tid & 1) * 32;
#pragma unroll
        for (int i = 0; i < 8; i++) {
            float4 v = *(const float4*)(Qh + (size_t)r * q_row_stride + c0 + i * 4);
            *(float4*)&sQ[r * ASTR + c0 + i * 4] = v;
        }
    }
    __syncthreads();

    // ---- extract warp's Q fragments (rows wq+g, wq+g+8), hi/lo split ----
    uint32_t qh[8][4], ql[8][4];
#pragma unroll
    for (int kc = 0; kc < 8; kc++) {
        const int col = 8 * kc + tg;
        hilo(sQ[(wq + g) * ASTR + col],         qh[kc][0], ql[kc][0]);
        hilo(sQ[(wq + g + 8) * ASTR + col],     qh[kc][1], ql[kc][1]);
        hilo(sQ[(wq + g) * ASTR + col + 4],     qh[kc][2], ql[kc][2]);
        hilo(sQ[(wq + g + 8) * ASTR + col + 4], qh[kc][3], ql[kc][3]);
    }

    float mloc[2] = {-INFINITY, -INFINITY};
    float lloc[2] = {0.f, 0.f};

    // ================= Phase 1: scores + streaming stats =================
    for (int kb = 0; kb < 8; kb++) {
        __syncthreads();
        {
            const int r  = tid >> 1;
            const int c0 = (tid & 1) * 32;
#pragma unroll
            for (int i = 0; i < 8; i++) {
                float4 v = *(const float4*)(Kh + (size_t)(kb * 128 + r) * DH + c0 + i * 4);
                *(float4*)&sKV[r * ASTR + c0 + i * 4] = v;
            }
        }
        __syncthreads();

#pragma unroll 1
        for (int nt = 0; nt < 16; nt++) {
            float acc[4] = {0.f, 0.f, 0.f, 0.f};
#pragma unroll
            for (int kc = 0; kc < 8; kc++) {
                uint32_t bh[2], bl[2];
                hilo(sKV[(8 * nt + g) * ASTR + 8 * kc + tg],     bh[0], bl[0]);
                hilo(sKV[(8 * nt + g) * ASTR + 8 * kc + tg + 4], bh[1], bl[1]);
                mma_tf32(acc, qh[kc], bh);
                mma_tf32(acc, qh[kc], bl);
                mma_tf32(acc, ql[kc], bh);
            }
#pragma unroll
            for (int j = 0; j < 4; j++) acc[j] *= 8.f;   // scale = sqrt(d_head)

            // cache scaled scores (c-layout: rows g,g+8; cols 8nt+2tg,+1)
            *(float2*)(Sh + (size_t)(wq + g) * SEQ + kb * 128 + 8 * nt + 2 * tg)
                = make_float2(acc[0], acc[1]);
            *(float2*)(Sh + (size_t)(wq + g + 8) * SEQ + kb * 128 + 8 * nt + 2 * tg)
                = make_float2(acc[2], acc[3]);

            // streaming per-thread (m,l) update, rows 0 (g) and 1 (g+8)
            {
                const float mx = fmaxf(acc[0], acc[1]);
                const float nm = fmaxf(mloc[0], mx);
                lloc[0] = lloc[0] * __expf(mloc[0] - nm) + __expf(acc[0] - nm) + __expf(acc[1] - nm);
                mloc[0] = nm;
            }
            {
                const float mx = fmaxf(acc[2], acc[3]);
                const float nm = fmaxf(mloc[1], mx);
                lloc[1] = lloc[1] * __expf(mloc[1] - nm) + __expf(acc[2] - nm) + __expf(acc[3] - nm);
                mloc[1] = nm;
            }
        }
    }

    // ---- merge (m,l) across the quad (4 threads share each row) ----
    float invl[2];
#pragma unroll
    for (int i = 0; i < 2; i++) {
#pragma unroll
        for (int off = 1; off <= 2; off <<= 1) {
            const float om = __shfl_xor_sync(0xffffffffu, mloc[i], off);
            const float ol = __shfl_xor_sync(0xffffffffu, lloc[i], off);
            const float nm = fmaxf(mloc[i], om);
            lloc[i] = lloc[i] * __expf(mloc[i] - nm) + ol * __expf(om - nm);
            mloc[i] = nm;
        }
        invl[i] = 1.f / lloc[i];
    }

    // ================= Phase 2: probabilities + PV =================
    float ctx[8][4];
#pragma unroll
    for (int nt = 0; nt < 8; nt++)
#pragma unroll
        for (int j = 0; j < 4; j++) ctx[nt][j] = 0.f;

    for (int kb = 0; kb < 8; kb++) {
        __syncthreads();
        {
            const int r  = tid >> 1;
            const int c0 = (tid & 1) * 32;
#pragma unroll
            for (int i = 0; i < 8; i++) {
                float4 v = *(const float4*)(Vh + (size_t)(kb * 128 + r) * DH + c0 + i * 4);
                *(float4*)&sKV[r * ASTR + c0 + i * 4] = v;
            }
        }
        __syncthreads();

#pragma unroll 1
        for (int kc = 0; kc < 16; kc++) {
            const int cbase = kb * 128 + 8 * kc;
            // read scores at A-fragment positions
            const float s0 = Sh[(size_t)(wq + g) * SEQ + cbase + tg];
            const float s1 = Sh[(size_t)(wq + g + 8) * SEQ + cbase + tg];
            const float s2 = Sh[(size_t)(wq + g) * SEQ + cbase + tg + 4];
            const float s3 = Sh[(size_t)(wq + g + 8) * SEQ + cbase + tg + 4];
            const float p0 = __expf(s0 - mloc[0]) * invl[0];
            const float p1 = __expf(s1 - mloc[1]) * invl[1];
            const float p2 = __expf(s2 - mloc[0]) * invl[0];
            const float p3 = __expf(s3 - mloc[1]) * invl[1];

            if (attn_out) {
                float* ao = attn_out + ((size_t)H * SEQ + q0) * SEQ;
                ao[(size_t)(wq + g) * SEQ + cbase + tg]         = p0;
                ao[(size_t)(wq + g + 8) * SEQ + cbase + tg]     = p1;
                ao[(size_t)(wq + g) * SEQ + cbase + tg + 4]     = p2;
                ao[(size_t)(wq + g + 8) * SEQ + cbase + tg + 4] = p3;
            }

            uint32_t ph[4], pl[4];
            hilo(p0, ph[0], pl[0]);
            hilo(p1, ph[1], pl[1]);
            hilo(p2, ph[2], pl[2]);
            hilo(p3, ph[3], pl[3]);

#pragma unroll
            for (int nt = 0; nt < 8; nt++) {
                uint32_t vh[2], vl[2];
                hilo(sKV[(8 * kc + tg) * ASTR + 8 * nt + g],     vh[0], vl[0]);
                hilo(sKV[(8 * kc + tg + 4) * ASTR + 8 * nt + g], vh[1], vl[1]);
                mma_tf32(ctx[nt], ph, vh);
                mma_tf32(ctx[nt], ph, vl);
                mma_tf32(ctx[nt], pl, vh);
            }
        }
    }

    // ---- write ctx into interleaved ctot (row stride 128) ----
#pragma unroll
    for (int nt = 0; nt < 8; nt++) {
        const int c = ctx_off + 8 * nt + 2 * tg;
        *(float2*)(ctx_out + ((size_t)H * SEQ + q0 + wq + g) * 128 + c)
            = make_float2(ctx[nt][0], ctx[nt][1]);
        *(float2*)(ctx_out + ((size_t)H * SEQ + q0 + wq + g + 8) * 128 + c)
            = make_float2(ctx[nt][2], ctx[nt][3]);
    }
}

// ---------------------------------------------------------------------------
// Row LayerNorm over ND=2048
// ---------------------------------------------------------------------------
__global__ void ln_kernel(const float* __restrict__ X, const float* __restrict__ gamma,
                          const float* __restrict__ beta, float* __restrict__ Y)
{
    __shared__ float red[64];
    const int row = blockIdx.x;
    const float* x = X + (size_t)row * ND;
    float sum = 0.f, sq = 0.f;
    for (int i = threadIdx.x; i < ND; i += blockDim.x) {
        const float v = x[i];
        sum += v; sq += v * v;
    }
#pragma unroll
    for (int off = 16; off; off >>= 1) {
        sum += __shfl_xor_sync(0xffffffffu, sum, off);
        sq  += __shfl_xor_sync(0xffffffffu, sq, off);
    }
    const int warp = threadIdx.x >> 5, lane = threadIdx.x & 31;
    if (lane == 0) { red[warp] = sum; red[warp + 32] = sq; }
    __syncthreads();
    if (warp == 0) {
        sum = (lane < 8) ? red[lane] : 0.f;
        sq  = (lane < 8) ? red[lane + 32] : 0.f;
#pragma unroll
        for (int off = 4; off; off >>= 1) {
            sum += __shfl_xor_sync(0xffffffffu, sum, off);
            sq  += __shfl_xor_sync(0xffffffffu, sq, off);
        }
        if (lane == 0) { red[0] = sum; red[1] = sq; }
    }
    __syncthreads();
    const float mu  = red[0] * (1.f / ND);
    const float var = red[1] * (1.f / ND) - mu * mu;
    const float inv = rsqrtf(var + 1e-5f);
    float* y = Y + (size_t)row * ND;
    for (int i = threadIdx.x; i < ND; i += blockDim.x)
        y[i] = (x[i] - mu) * inv * gamma[i] + beta[i];
}

// ---------------------------------------------------------------------------
extern "C" void kernel_launch(void* const* d_in, const int* in_sizes, int n_in,
                              void* d_out, int out_size)
{
    const float* k_in  = (const float*)d_in[0];
    const float* v_in  = (const float*)d_in[1];
    const float* q_in  = (const float*)d_in[2];
    const float* r_in  = (const float*)d_in[3];
    const float* Wr    = (const float*)d_in[4];
    const float* br    = (const float*)d_in[5];
    const float* Wf    = (const float*)d_in[6];
    const float* bf    = (const float*)d_in[7];
    const float* gamma = (const float*)d_in[8];
    const float* beta  = (const float*)d_in[9];

    float* out      = (float*)d_out;
    float* y_out    = out;
    float* attn_out = out + (size_t)MROWS * ND;

    float* rp;     cudaGetSymbolAddress((void**)&rp, g_rp);
    float* ctot;   cudaGetSymbolAddress((void**)&ctot, g_ctot);
    float* scores; cudaGetSymbolAddress((void**)&scores, g_scores);

    cudaFuncSetAttribute(attn_mma, cudaFuncAttributeMaxDynamicSharedMemorySize, ATTN_SMEM);

    // 1) rp = r @ Wr^T + br
    dim3 g1(ND / 128, MROWS / 128);
    gemm_tf32<<<g1, 256>>>(r_in, Wr, br, nullptr, rp, MROWS, ND, MD);

    // 2) pass 1: attn1 -> d_out, ctx1 -> ctot[..,0:64]
    dim3 ga(SEQ / 128, HEADS);
    attn_mma<<<ga, 256, ATTN_SMEM>>>(q_in, SEQ * DH, DH, k_in, v_in, scores, attn_out, ctot, 0);

    // 3) pass 2: queries = ctx1 (stride 128), ctx2 -> ctot[..,64:128]
    attn_mma<<<ga, 256, ATTN_SMEM>>>(ctot, SEQ * 128, 128, k_in, v_in, scores, nullptr, ctot, 64);

    // 4) x = ctot @ Wf^T + bf + rp
    gemm_tf32<<<g1, 256>>>(ctot, Wf, bf, rp, rp, MROWS, ND, ND);

    // 5) y = LayerNorm(x)
    ln_kernel<<<MROWS, 256>>>(rp, gamma, beta, y_out);
}

// round 9
// speedup vs baseline: 1.0175x; 1.0175x over previous
#include <cuda_runtime.h>
#include <cstdint>
#include <math.h>

// Problem dims (fixed)
#define SEQ   1024
#define DH    64
#define HEADS 64          // bz*16
#define MD    1024        // model_dim
#define ND    2048        // model_dim * n_scale
#define MROWS 4096        // bz*seq

// Scratch (allocation-free rule: device globals)
__device__ float g_rp[(size_t)MROWS * ND];            // 32 MB
__device__ float g_ctot[(size_t)HEADS * SEQ * 128];   // 32 MB: ctx1/ctx2 interleaved
__device__ float g_scores[(size_t)HEADS * SEQ * SEQ]; // 256 MB: raw scaled scores

// ---------------------------------------------------------------------------
// Common MMA helpers
// ---------------------------------------------------------------------------
__device__ __forceinline__ uint32_t f2tf32(float x) {
    uint32_t r;
    asm("cvt.rna.tf32.f32 %0, %1;" : "=r"(r) : "f"(x));
    return r;
}

// split x into tf32 hi + tf32 lo (x ~= hi + lo, |lo| <= 2^-11 |x|)
__device__ __forceinline__ void hilo(float x, uint32_t& h, uint32_t& l) {
    h = f2tf32(x);
    l = f2tf32(x - __uint_as_float(h));
}

__device__ __forceinline__ void mma_tf32(float* c, const uint32_t* a, const uint32_t* b) {
    asm volatile(
        "mma.sync.aligned.m16n8k8.row.col.f32.tf32.tf32.f32 "
        "{%0,%1,%2,%3},{%4,%5,%6,%7},{%8,%9},{%0,%1,%2,%3};"
        : "+f"(c[0]), "+f"(c[1]), "+f"(c[2]), "+f"(c[3])
        : "r"(a[0]), "r"(a[1]), "r"(a[2]), "r"(a[3]), "r"(b[0]), "r"(b[1]));
}

__device__ __forceinline__ void cp16(void* smem, const void* gmem) {
    uint32_t s = (uint32_t)__cvta_generic_to_shared(smem);
    asm volatile("cp.async.ca.shared.global [%0], [%1], 16;" :: "r"(s), "l"(gmem));
}
#define CP_COMMIT() asm volatile("cp.async.commit_group;")
#define CP_WAIT1()  asm volatile("cp.async.wait_group 1;")
#define CP_WAIT0()  asm volatile("cp.async.wait_group 0;")

// ---------------------------------------------------------------------------
// TF32 GEMM, cp.async 3-stage pipeline: C = A B^T + bias (+ addend)
// BM=BN=128, BK=16, 256 threads, warp tile 32x64. Dynamic smem 60 KB.
// ---------------------------------------------------------------------------
#define GSTR 20
#define GEMM_STAGE (128 * GSTR)
#define GEMM_SMEM (3 * 2 * GEMM_STAGE * 4)   // 61,440 B

__global__ void __launch_bounds__(256, 2) gemm_tf32(
    const float* __restrict__ A, const float* __restrict__ B,
    const float* __restrict__ bias, const float* __restrict__ addend,
    float* __restrict__ C, int M, int N, int K)
{
    extern __shared__ float gsm[];
    float* As = gsm;                       // [3][GEMM_STAGE]
    float* Bs = gsm + 3 * GEMM_STAGE;      // [3][GEMM_STAGE]

    const int tid  = threadIdx.x;
    const int warp = tid >> 5, lane = tid & 31;
    const int wm = (warp >> 1) * 32;
    const int wn = (warp & 1) * 64;
    const int m0 = blockIdx.y * 128, n0 = blockIdx.x * 128;
    const int g  = lane >> 2;
    const int tg = lane & 3;

    float acc[2][8][4];
#pragma unroll
    for (int i = 0; i < 2; i++)
#pragma unroll
        for (int j = 0; j < 8; j++)
#pragma unroll
            for (int r = 0; r < 4; r++) acc[i][j][r] = 0.f;

    auto load_stage = [&](int s, int k0) {
#pragma unroll
        for (int i = 0; i < 2; i++) {
            const int idx = tid + 256 * i;
            const int row = idx >> 2;
            const int cq  = (idx & 3) * 4;
            cp16(&As[s * GEMM_STAGE + row * GSTR + cq], A + (size_t)(m0 + row) * K + k0 + cq);
            cp16(&Bs[s * GEMM_STAGE + row * GSTR + cq], B + (size_t)(n0 + row) * K + k0 + cq);
        }
    };

    const int ntiles = K / 16;
    load_stage(0, 0);  CP_COMMIT();
    load_stage(1, 16); CP_COMMIT();

    for (int t = 0; t < ntiles; t++) {
        if (t + 1 < ntiles) { CP_WAIT1(); } else { CP_WAIT0(); }
        __syncthreads();
        if (t + 2 < ntiles) {
            load_stage((t + 2) % 3, (t + 2) * 16);
            CP_COMMIT();
        }

        const float* Ab = As + (t % 3) * GEMM_STAGE;
        const float* Bb = Bs + (t % 3) * GEMM_STAGE;
#pragma unroll
        for (int ks = 0; ks < 16; ks += 8) {
            uint32_t afrag[2][4], bfrag[8][2];
#pragma unroll
            for (int mi = 0; mi < 2; mi++) {
                const int row = wm + mi * 16 + g;
                afrag[mi][0] = f2tf32(Ab[row * GSTR + ks + tg]);
                afrag[mi][1] = f2tf32(Ab[(row + 8) * GSTR + ks + tg]);
                afrag[mi][2] = f2tf32(Ab[row * GSTR + ks + tg + 4]);
                afrag[mi][3] = f2tf32(Ab[(row + 8) * GSTR + ks + tg + 4]);
            }
#pragma unroll
            for (int ni = 0; ni < 8; ni++) {
                const int col = wn + ni * 8 + g;
                bfrag[ni][0] = f2tf32(Bb[col * GSTR + ks + tg]);
                bfrag[ni][1] = f2tf32(Bb[col * GSTR + ks + tg + 4]);
            }
#pragma unroll
            for (int mi = 0; mi < 2; mi++)
#pragma unroll
                for (int ni = 0; ni < 8; ni++)
                    mma_tf32(acc[mi][ni], afrag[mi], bfrag[ni]);
        }
    }

    __syncthreads();
#pragma unroll
    for (int mi = 0; mi < 2; mi++) {
#pragma unroll
        for (int ni = 0; ni < 8; ni++) {
            const int m = m0 + wm + mi * 16 + g;
            const int n = n0 + wn + ni * 8 + tg * 2;
            const float bx = bias[n], by = bias[n + 1];
            float2 v0 = make_float2(acc[mi][ni][0] + bx, acc[mi][ni][1] + by);
            float2 v1 = make_float2(acc[mi][ni][2] + bx, acc[mi][ni][3] + by);
            if (addend) {
                float2 d0 = *(const float2*)(addend + (size_t)m * N + n);
                float2 d1 = *(const float2*)(addend + (size_t)(m + 8) * N + n);
                v0.x += d0.x; v0.y += d0.y; v1.x += d1.x; v1.y += d1.y;
            }
            *(float2*)(C + (size_t)m * N + n) = v0;
            *(float2*)(C + (size_t)(m + 8) * N + n) = v1;
        }
    }
}

// ---------------------------------------------------------------------------
// Tensor-core attention (tf32x3 = fp32-equivalent precision).
// Block: 128 q rows x one head; 8 warps, warp w owns q rows [16w,16w+16).
// K/V tiles are hi/lo-split ONCE per tile into smem uint2 pairs, so the
// inner loops are pure LDS.64 + MMA (no per-warp redundant cvt chains).
// Phase 1: scores = 8*(Q K^T) -> g_scores + streaming (m,l).
// Phase 2: p = exp(s-m)/l from cached scores, optional attn out, ctx = P V.
// ---------------------------------------------------------------------------
#define ASTR 68
#define ATTN_SMEM (128 * ASTR * 4 + 128 * ASTR * 8)   // sQ + uint2 KV = 104,448 B

__global__ void __launch_bounds__(256, 2)
attn_mma(const float* __restrict__ Qbase, int q_head_stride, int q_row_stride,
         const float* __restrict__ Kin, const float* __restrict__ Vin,
         float* __restrict__ scores,
         float* __restrict__ attn_out,   // nullptr for pass 2
         float* __restrict__ ctx_out, int ctx_off)
{
    extern __shared__ char smraw[];
    float* sQ  = (float*)smraw;                        // [128][ASTR] floats
    uint2* sKV = (uint2*)(smraw + 128 * ASTR * 4);     // [128][ASTR] (hi,lo) pairs

    const int H   = blockIdx.y;
    const int q0  = blockIdx.x * 128;
    const int tid = threadIdx.x;
    const int w   = tid >> 5, lane = tid & 31;
    const int g   = lane >> 2, tg = lane & 3;
    const int wq  = w * 16;

    const float* Qh = Qbase + (size_t)H * q_head_stride + (size_t)q0 * q_row_stride;
    const float* Kh = Kin + (size_t)H * (SEQ * DH);
    const float* Vh = Vin + (size_t)H * (SEQ * DH);
    float* Sh = scores + (size_t)H * SEQ * SEQ + (size_t)q0 * SEQ;

    const int lr  = tid >> 1;            // loader row 0..127
    const int lc0 = (tid & 1) * 32;      // loader col base

    // ---- load Q tile (128x64) into smem, coalesced ----
#pragma unroll
    for (int i = 0; i < 8; i++) {
        float4 v = *(const float4*)(Qh + (size_t)lr * q_row_stride + lc0 + i * 4);
        *(float4*)&sQ[lr * ASTR + lc0 + i * 4] = v;
    }
    __syncthreads();

    // ---- extract warp's Q fragments (rows wq+g, wq+g+8), hi/lo split ----
    uint32_t qh[8][4], ql[8][4];
#pragma unroll
    for (int kc = 0; kc < 8; kc++) {
        const int col = 8 * kc + tg;
        hilo(sQ[(wq + g) * ASTR + col],         qh[kc][0], ql[kc][0]);
        hilo(sQ[(wq + g + 8) * ASTR + col],     qh[kc][1], ql[kc][1]);
        hilo(sQ[(wq + g) * ASTR + col + 4],     qh[kc][2], ql[kc][2]);
        hilo(sQ[(wq + g + 8) * ASTR + col + 4], qh[kc][3], ql[kc][3]);
    }

    float mloc[2] = {-INFINITY, -INFINITY};
    float lloc[2] = {0.f, 0.f};

    // ================= Phase 1: scores + streaming stats =================
    for (int kb = 0; kb < 8; kb++) {
        __syncthreads();
        // load + split K tile into (hi,lo) pairs
#pragma unroll
        for (int i = 0; i < 8; i++) {
            float4 v = *(const float4*)(Kh + (size_t)(kb * 128 + lr) * DH + lc0 + i * 4);
            uint32_t h0, l0, h1, l1, h2, l2, h3, l3;
            hilo(v.x, h0, l0); hilo(v.y, h1, l1);
            hilo(v.z, h2, l2); hilo(v.w, h3, l3);
            uint2* dst = &sKV[lr * ASTR + lc0 + i * 4];
            *(uint4*)(dst)     = make_uint4(h0, l0, h1, l1);
            *(uint4*)(dst + 2) = make_uint4(h2, l2, h3, l3);
        }
        __syncthreads();

#pragma unroll 1
        for (int nt = 0; nt < 16; nt++) {
            float acc[4] = {0.f, 0.f, 0.f, 0.f};
#pragma unroll
            for (int kc = 0; kc < 8; kc++) {
                const uint2 b0 = sKV[(8 * nt + g) * ASTR + 8 * kc + tg];
                const uint2 b1 = sKV[(8 * nt + g) * ASTR + 8 * kc + tg + 4];
                uint32_t bh[2] = {b0.x, b1.x};
                uint32_t bl[2] = {b0.y, b1.y};
                mma_tf32(acc, qh[kc], bh);
                mma_tf32(acc, qh[kc], bl);
                mma_tf32(acc, ql[kc], bh);
            }
#pragma unroll
            for (int j = 0; j < 4; j++) acc[j] *= 8.f;   // scale = sqrt(d_head)

            // cache scaled scores (c-layout: rows g,g+8; cols 8nt+2tg,+1)
            *(float2*)(Sh + (size_t)(wq + g) * SEQ + kb * 128 + 8 * nt + 2 * tg)
                = make_float2(acc[0], acc[1]);
            *(float2*)(Sh + (size_t)(wq + g + 8) * SEQ + kb * 128 + 8 * nt + 2 * tg)
                = make_float2(acc[2], acc[3]);

            // streaming per-thread (m,l) update
            {
                const float mx = fmaxf(acc[0], acc[1]);
                const float nm = fmaxf(mloc[0], mx);
                lloc[0] = lloc[0] * __expf(mloc[0] - nm) + __expf(acc[0] - nm) + __expf(acc[1] - nm);
                mloc[0] = nm;
            }
            {
                const float mx = fmaxf(acc[2], acc[3]);
                const float nm = fmaxf(mloc[1], mx);
                lloc[1] = lloc[1] * __expf(mloc[1] - nm) + __expf(acc[2] - nm) + __expf(acc[3] - nm);
                mloc[1] = nm;
            }
        }
    }

    // ---- merge (m,l) across the quad (4 threads share each row) ----
    float invl[2];
#pragma unroll
    for (int i = 0; i < 2; i++) {
#pragma unroll
        for (int off = 1; off <= 2; off <<= 1) {
            const float om = __shfl_xor_sync(0xffffffffu, mloc[i], off);
            const float ol = __shfl_xor_sync(0xffffffffu, lloc[i], off);
            const float nm = fmaxf(mloc[i], om);
            lloc[i] = lloc[i] * __expf(mloc[i] - nm) + ol * __expf(om - nm);
            mloc[i] = nm;
        }
        invl[i] = 1.f / lloc[i];
    }

    // ================= Phase 2: probabilities + PV =================
    float ctx[8][4];
#pragma unroll
    for (int nt = 0; nt < 8; nt++)
#pragma unroll
        for (int j = 0; j < 4; j++) ctx[nt][j] = 0.f;

    for (int kb = 0; kb < 8; kb++) {
        __syncthreads();
        // load + split V tile into (hi,lo) pairs
#pragma unroll
        for (int i = 0; i < 8; i++) {
            float4 v = *(const float4*)(Vh + (size_t)(kb * 128 + lr) * DH + lc0 + i * 4);
            uint32_t h0, l0, h1, l1, h2, l2, h3, l3;
            hilo(v.x, h0, l0); hilo(v.y, h1, l1);
            hilo(v.z, h2, l2); hilo(v.w, h3, l3);
            uint2* dst = &sKV[lr * ASTR + lc0 + i * 4];
            *(uint4*)(dst)     = make_uint4(h0, l0, h1, l1);
            *(uint4*)(dst + 2) = make_uint4(h2, l2, h3, l3);
        }
        __syncthreads();

#pragma unroll 1
        for (int kc = 0; kc < 16; kc++) {
            const int cbase = kb * 128 + 8 * kc;
            // read scores at A-fragment positions
            const float s0 = Sh[(size_t)(wq + g) * SEQ + cbase + tg];
            const float s1 = Sh[(size_t)(wq + g + 8) * SEQ + cbase + tg];
            const float s2 = Sh[(size_t)(wq + g) * SEQ + cbase + tg + 4];
            const float s3 = Sh[(size_t)(wq + g + 8) * SEQ + cbase + tg + 4];
            const float p0 = __expf(s0 - mloc[0]) * invl[0];
            const float p1 = __expf(s1 - mloc[1]) * invl[1];
            const float p2 = __expf(s2 - mloc[0]) * invl[0];
            const float p3 = __expf(s3 - mloc[1]) * invl[1];

            if (attn_out) {
                float* ao = attn_out + ((size_t)H * SEQ + q0) * SEQ;
                ao[(size_t)(wq + g) * SEQ + cbase + tg]         = p0;
                ao[(size_t)(wq + g + 8) * SEQ + cbase + tg]     = p1;
                ao[(size_t)(wq + g) * SEQ + cbase + tg + 4]     = p2;
                ao[(size_t)(wq + g + 8) * SEQ + cbase + tg + 4] = p3;
            }

            uint32_t ph[4], pl[4];
            hilo(p0, ph[0], pl[0]);
            hilo(p1, ph[1], pl[1]);
            hilo(p2, ph[2], pl[2]);
            hilo(p3, ph[3], pl[3]);

#pragma unroll
            for (int nt = 0; nt < 8; nt++) {
                const uint2 v0 = sKV[(8 * kc + tg) * ASTR + 8 * nt + g];
                const uint2 v1 = sKV[(8 * kc + tg + 4) * ASTR + 8 * nt + g];
                uint32_t vh[2] = {v0.x, v1.x};
                uint32_t vl[2] = {v0.y, v1.y};
                mma_tf32(ctx[nt], ph, vh);
                mma_tf32(ctx[nt], ph, vl);
                mma_tf32(ctx[nt], pl, vh);
            }
        }
    }

    // ---- write ctx into interleaved ctot (row stride 128) ----
#pragma unroll
    for (int nt = 0; nt < 8; nt++) {
        const int c = ctx_off + 8 * nt + 2 * tg;
        *(float2*)(ctx_out + ((size_t)H * SEQ + q0 + wq + g) * 128 + c)
            = make_float2(ctx[nt][0], ctx[nt][1]);
        *(float2*)(ctx_out + ((size_t)H * SEQ + q0 + wq + g + 8) * 128 + c)
            = make_float2(ctx[nt][2], ctx[nt][3]);
    }
}

// ---------------------------------------------------------------------------
// Row LayerNorm over ND=2048
// ---------------------------------------------------------------------------
__global__ void ln_kernel(const float* __restrict__ X, const float* __restrict__ gamma,
                          const float* __restrict__ beta, float* __restrict__ Y)
{
    __shared__ float red[64];
    const int row = blockIdx.x;
    const float* x = X + (size_t)row * ND;
    float sum = 0.f, sq = 0.f;
    for (int i = threadIdx.x; i < ND; i += blockDim.x) {
        const float v = x[i];
        sum += v; sq += v * v;
    }
#pragma unroll
    for (int off = 16; off; off >>= 1) {
        sum += __shfl_xor_sync(0xffffffffu, sum, off);
        sq  += __shfl_xor_sync(0xffffffffu, sq, off);
    }
    const int warp = threadIdx.x >> 5, lane = threadIdx.x & 31;
    if (lane == 0) { red[warp] = sum; red[warp + 32] = sq; }
    __syncthreads();
    if (warp == 0) {
        sum = (lane < 8) ? red[lane] : 0.f;
        sq  = (lane < 8) ? red[lane + 32] : 0.f;
#pragma unroll
        for (int off = 4; off; off >>= 1) {
            sum += __shfl_xor_sync(0xffffffffu, sum, off);
            sq  += __shfl_xor_sync(0xffffffffu, sq, off);
        }
        if (lane == 0) { red[0] = sum; red[1] = sq; }
    }
    __syncthreads();
    const float mu  = red[0] * (1.f / ND);
    const float var = red[1] * (1.f / ND) - mu * mu;
    const float inv = rsqrtf(var + 1e-5f);
    float* y = Y + (size_t)row * ND;
    for (int i = threadIdx.x; i < ND; i += blockDim.x)
        y[i] = (x[i] - mu) * inv * gamma[i] + beta[i];
}

// ---------------------------------------------------------------------------
extern "C" void kernel_launch(void* const* d_in, const int* in_sizes, int n_in,
                              void* d_out, int out_size)
{
    const float* k_in  = (const float*)d_in[0];
    const float* v_in  = (const float*)d_in[1];
    const float* q_in  = (const float*)d_in[2];
    const float* r_in  = (const float*)d_in[3];
    const float* Wr    = (const float*)d_in[4];
    const float* br    = (const float*)d_in[5];
    const float* Wf    = (const float*)d_in[6];
    const float* bf    = (const float*)d_in[7];
    const float* gamma = (const float*)d_in[8];
    const float* beta  = (const float*)d_in[9];

    float* out      = (float*)d_out;
    float* y_out    = out;
    float* attn_out = out + (size_t)MROWS * ND;

    float* rp;     cudaGetSymbolAddress((void**)&rp, g_rp);
    float* ctot;   cudaGetSymbolAddress((void**)&ctot, g_ctot);
    float* scores; cudaGetSymbolAddress((void**)&scores, g_scores);

    cudaFuncSetAttribute(attn_mma, cudaFuncAttributeMaxDynamicSharedMemorySize, ATTN_SMEM);
    cudaFuncSetAttribute(gemm_tf32, cudaFuncAttributeMaxDynamicSharedMemorySize, GEMM_SMEM);

    // 1) rp = r @ Wr^T + br
    dim3 g1(ND / 128, MROWS / 128);
    gemm_tf32<<<g1, 256, GEMM_SMEM>>>(r_in, Wr, br, nullptr, rp, MROWS, ND, MD);

    // 2) pass 1: attn1 -> d_out, ctx1 -> ctot[..,0:64]
    dim3 ga(SEQ / 128, HEADS);
    attn_mma<<<ga, 256, ATTN_SMEM>>>(q_in, SEQ * DH, DH, k_in, v_in, scores, attn_out, ctot, 0);

    // 3) pass 2: queries = ctx1 (stride 128), ctx2 -> ctot[..,64:128]
    attn_mma<<<ga, 256, ATTN_SMEM>>>(ctot, SEQ * 128, 128, k_in, v_in, scores, nullptr, ctot, 64);

    // 4) x = ctot @ Wf^T + bf + rp
    gemm_tf32<<<g1, 256, GEMM_SMEM>>>(ctot, Wf, bf, rp, rp, MROWS, ND, ND);

    // 5) y = LayerNorm(x)
    ln_kernel<<<MROWS, 256>>>(rp, gamma, beta, y_out);
}